// round 4
// baseline (speedup 1.0000x reference)
#include <cuda_runtime.h>
#include <cuda_bf16.h>

#define N_NODES 50000
#define N_EDGES 800000
#define NV4 32            // float4 per 128-float row

// ---- device scratch (no dynamic allocs allowed) ----
__device__ float4 g_bufA[(size_t)N_NODES * NV4];
__device__ float4 g_bufB[(size_t)N_NODES * NV4];
__device__ float4 g_m   [(size_t)N_NODES * NV4];
__device__ int    g_out_cnt[N_NODES];
__device__ int    g_in_cnt[N_NODES];
__device__ int    g_cursor[N_NODES];
__device__ int    g_off[N_NODES + 1];
__device__ int    g_csr_src[N_EDGES];
__device__ float  g_out_inv[N_NODES];
__device__ float  g_in_inv[N_NODES];

// ---------------- CSR build ----------------
__global__ void k_init() {
    int i = blockIdx.x * blockDim.x + threadIdx.x;
    if (i < N_NODES) { g_out_cnt[i] = 0; g_in_cnt[i] = 0; g_cursor[i] = 0; }
}

__global__ void k_deg(const int* __restrict__ src,
                      const int* __restrict__ dst) {
    int e = blockIdx.x * blockDim.x + threadIdx.x;
    if (e < N_EDGES) {
        unsigned s = (unsigned)src[e];
        unsigned d = (unsigned)dst[e];
        if (s < N_NODES) atomicAdd(&g_out_cnt[s], 1);
        if (d < N_NODES) atomicAdd(&g_in_cnt[d], 1);
    }
}

// one-block exclusive scan of in_cnt -> g_off, plus inverse-sqrt degree tables
__global__ void k_scan() {
    const int T = 1024;
    const int CH = (N_NODES + T - 1) / T;   // 49
    __shared__ int part[T];
    int t = threadIdx.x;
    int base = t * CH;
    int s = 0;
    for (int i = 0; i < CH; i++) {
        int idx = base + i;
        if (idx < N_NODES) s += g_in_cnt[idx];
    }
    part[t] = s;
    __syncthreads();
    for (int o = 1; o < T; o <<= 1) {
        int v = (t >= o) ? part[t - o] : 0;
        __syncthreads();
        part[t] += v;
        __syncthreads();
    }
    int run = (t == 0) ? 0 : part[t - 1];
    for (int i = 0; i < CH; i++) {
        int idx = base + i;
        if (idx < N_NODES) { g_off[idx] = run; run += g_in_cnt[idx]; }
    }
    if (t == T - 1) g_off[N_NODES] = run;
    for (int idx = t; idx < N_NODES; idx += T) {
        g_out_inv[idx] = rsqrtf((float)max(g_out_cnt[idx], 1));
        g_in_inv[idx]  = rsqrtf((float)max(g_in_cnt[idx], 1));
    }
}

__global__ void k_fill(const int* __restrict__ src,
                       const int* __restrict__ dst) {
    int e = blockIdx.x * blockDim.x + threadIdx.x;
    if (e < N_EDGES) {
        unsigned s = (unsigned)src[e];
        unsigned d = (unsigned)dst[e];
        if (s < N_NODES && d < N_NODES) {
            int pos = atomicAdd(&g_cursor[d], 1);
            int idx = g_off[d] + pos;
            if ((unsigned)idx < N_EDGES) g_csr_src[idx] = (int)s;
        }
    }
}

// bufA = h * out_deg^{-1/2}  (src-side normalization for layer 0)
__global__ void k_scale0(const float4* __restrict__ h) {
    int i = blockIdx.x * blockDim.x + threadIdx.x;
    if (i < N_NODES * NV4) {
        float sc = g_out_inv[i >> 5];
        float4 v = h[i];
        v.x *= sc; v.y *= sc; v.z *= sc; v.w *= sc;
        g_bufA[i] = v;
    }
}

// ---------------- aggregation: m[n] = in_inv[n] * sum_{e: dst=n} x[src[e]] ----
// one warp per node; in_sel: 0 -> bufA, 1 -> bufB
__global__ void __launch_bounds__(256) k_agg(int in_sel) {
    const float4* __restrict__ xin = in_sel ? g_bufB : g_bufA;
    int warp = threadIdx.x >> 5;
    int lane = threadIdx.x & 31;
    int n = blockIdx.x * 8 + warp;

    int beg = g_off[n], end = g_off[n + 1];
    float4 acc = make_float4(0.f, 0.f, 0.f, 0.f);
    int k = beg;
    for (; k + 3 < end; k += 4) {
        int s0 = g_csr_src[k + 0];
        int s1 = g_csr_src[k + 1];
        int s2 = g_csr_src[k + 2];
        int s3 = g_csr_src[k + 3];
        float4 v0 = xin[s0 * NV4 + lane];
        float4 v1 = xin[s1 * NV4 + lane];
        float4 v2 = xin[s2 * NV4 + lane];
        float4 v3 = xin[s3 * NV4 + lane];
        acc.x += v0.x + v1.x + v2.x + v3.x;
        acc.y += v0.y + v1.y + v2.y + v3.y;
        acc.z += v0.z + v1.z + v2.z + v3.z;
        acc.w += v0.w + v1.w + v2.w + v3.w;
    }
    for (; k < end; ++k) {
        int s = g_csr_src[k];
        float4 v = xin[s * NV4 + lane];
        acc.x += v.x; acc.y += v.y; acc.z += v.z; acc.w += v.w;
    }
    float sc = g_in_inv[n];
    acc.x *= sc; acc.y *= sc; acc.z *= sc; acc.w *= sc;
    g_m[n * NV4 + lane] = acc;
}

// ---------------- GEMM: out = relu(m @ W + b) [* out_inv] ----------------
// out_sel: 0 -> g_bufA, 1 -> g_bufB, 2 -> dout (harness buffer)
__global__ void __launch_bounds__(256) k_gemm(int out_sel, float4* __restrict__ dout,
                                              const float* __restrict__ W,
                                              const float4* __restrict__ b4,
                                              int apply_out) {
    __shared__ __align__(16) float As[64][16];    // 4 KB
    __shared__ float4 Ws[16][32];                 // 8 KB

    float4* __restrict__ out = (out_sel == 0) ? g_bufA
                             : (out_sel == 1) ? g_bufB : dout;

    int tx = threadIdx.x & 31;       // column group (4 cols)
    int ty = threadIdx.x >> 5;       // row group (8 rows each)
    int row0 = blockIdx.x * 64;

    float4 bb = b4[tx];
    float4 acc[8];
    #pragma unroll
    for (int i = 0; i < 8; i++) acc[i] = bb;

    int a_node = row0 + (threadIdx.x >> 2);   // 0..63 within block
    int a_seg  = threadIdx.x & 3;             // which float4 of the 16-float strip

    for (int kt = 0; kt < 128; kt += 16) {
        float4 av = make_float4(0.f, 0.f, 0.f, 0.f);
        if (a_node < N_NODES) av = g_m[(size_t)a_node * NV4 + (kt >> 2) + a_seg];
        *((float4*)&As[threadIdx.x >> 2][a_seg * 4]) = av;

        const float4* Wg = (const float4*)(W + kt * 128);
        ((float4*)Ws)[threadIdx.x]       = Wg[threadIdx.x];
        ((float4*)Ws)[threadIdx.x + 256] = Wg[threadIdx.x + 256];
        __syncthreads();

        #pragma unroll
        for (int kk = 0; kk < 16; kk++) {
            float4 w = Ws[kk][tx];           // conflict-free LDS.128
            #pragma unroll
            for (int i = 0; i < 8; i++) {
                float a = As[ty * 8 + i][kk];   // warp-broadcast LDS
                acc[i].x = fmaf(a, w.x, acc[i].x);
                acc[i].y = fmaf(a, w.y, acc[i].y);
                acc[i].z = fmaf(a, w.z, acc[i].z);
                acc[i].w = fmaf(a, w.w, acc[i].w);
            }
        }
        __syncthreads();
    }

    #pragma unroll
    for (int i = 0; i < 8; i++) {
        int row = row0 + ty * 8 + i;
        if (row < N_NODES) {
            float4 a = acc[i];
            a.x = fmaxf(a.x, 0.f);
            a.y = fmaxf(a.y, 0.f);
            a.z = fmaxf(a.z, 0.f);
            a.w = fmaxf(a.w, 0.f);
            if (apply_out) {
                float sc = g_out_inv[row];
                a.x *= sc; a.y *= sc; a.z *= sc; a.w *= sc;
            }
            out[(size_t)row * NV4 + tx] = a;
        }
    }
}

extern "C" void kernel_launch(void* const* d_in, const int* in_sizes, int n_in,
                              void* d_out, int out_size) {
    const float* h   = (const float*)d_in[0];
    const int*   src = (const int*)d_in[1];    // int32: JAX x64 is disabled
    const int*   dst = (const int*)d_in[2];
    const float* W0 = (const float*)d_in[3];
    const float* b0 = (const float*)d_in[4];
    const float* W1 = (const float*)d_in[5];
    const float* b1 = (const float*)d_in[6];
    const float* W2 = (const float*)d_in[7];
    const float* b2 = (const float*)d_in[8];

    k_init<<<(N_NODES + 255) / 256, 256>>>();
    k_deg<<<(N_EDGES + 255) / 256, 256>>>(src, dst);
    k_scan<<<1, 1024>>>();
    k_fill<<<(N_EDGES + 255) / 256, 256>>>(src, dst);
    k_scale0<<<(N_NODES * NV4 + 255) / 256, 256>>>((const float4*)h);

    const int agg_grid  = N_NODES / 8;            // 6250, exact
    const int gemm_grid = (N_NODES + 63) / 64;    // 782

    // layer 0: bufA -> m -> bufB (out-scaled for next layer)
    k_agg <<<agg_grid, 256>>>(0);
    k_gemm<<<gemm_grid, 256>>>(1, nullptr, W0, (const float4*)b0, 1);
    // layer 1: bufB -> m -> bufA (out-scaled)
    k_agg <<<agg_grid, 256>>>(1);
    k_gemm<<<gemm_grid, 256>>>(0, nullptr, W1, (const float4*)b1, 1);
    // layer 2: bufA -> m -> d_out (no out-scale)
    k_agg <<<agg_grid, 256>>>(0);
    k_gemm<<<gemm_grid, 256>>>(2, (float4*)d_out, W2, (const float4*)b2, 0);
}

// round 6
// speedup vs baseline: 1.1163x; 1.1163x over previous
#include <cuda_runtime.h>
#include <cuda_bf16.h>
#include <cstdint>

#define N_NODES 50000
#define N_EDGES 800000
#define NV4 32            // float4 per 128-float row
#define D 128

// ---- device scratch (no dynamic allocs allowed) ----
__device__ float4 g_bufA[(size_t)N_NODES * NV4];
__device__ float4 g_bufB[(size_t)N_NODES * NV4];
__device__ float4 g_m   [(size_t)N_NODES * NV4];   // tf32-rounded aggregate
__device__ float  g_Wtf [3 * D * D];               // tf32-rounded weights
__device__ int    g_out_cnt[N_NODES];
__device__ int    g_in_cnt[N_NODES];
__device__ int    g_cursor[N_NODES];
__device__ int    g_off[N_NODES + 1];
__device__ int    g_csr_src[N_EDGES];
__device__ float  g_out_inv[N_NODES];
__device__ float  g_in_inv[N_NODES];

__device__ __forceinline__ float tf32r(float x) {
    uint32_t u;
    asm("cvt.rna.tf32.f32 %0, %1;" : "=r"(u) : "f"(x));
    return __uint_as_float(u);
}

// ---------------- CSR build ----------------
__global__ void k_init() {
    int i = blockIdx.x * blockDim.x + threadIdx.x;
    if (i < N_NODES) { g_out_cnt[i] = 0; g_in_cnt[i] = 0; g_cursor[i] = 0; }
}

__global__ void k_deg(const int* __restrict__ src,
                      const int* __restrict__ dst) {
    int e = blockIdx.x * blockDim.x + threadIdx.x;
    if (e < N_EDGES) {
        unsigned s = (unsigned)src[e];
        unsigned d = (unsigned)dst[e];
        if (s < N_NODES) atomicAdd(&g_out_cnt[s], 1);
        if (d < N_NODES) atomicAdd(&g_in_cnt[d], 1);
    }
}

__global__ void k_scan() {
    const int T = 1024;
    const int CH = (N_NODES + T - 1) / T;
    __shared__ int part[T];
    int t = threadIdx.x;
    int base = t * CH;
    int s = 0;
    for (int i = 0; i < CH; i++) {
        int idx = base + i;
        if (idx < N_NODES) s += g_in_cnt[idx];
    }
    part[t] = s;
    __syncthreads();
    for (int o = 1; o < T; o <<= 1) {
        int v = (t >= o) ? part[t - o] : 0;
        __syncthreads();
        part[t] += v;
        __syncthreads();
    }
    int run = (t == 0) ? 0 : part[t - 1];
    for (int i = 0; i < CH; i++) {
        int idx = base + i;
        if (idx < N_NODES) { g_off[idx] = run; run += g_in_cnt[idx]; }
    }
    if (t == T - 1) g_off[N_NODES] = run;
    for (int idx = t; idx < N_NODES; idx += T) {
        g_out_inv[idx] = rsqrtf((float)max(g_out_cnt[idx], 1));
        g_in_inv[idx]  = rsqrtf((float)max(g_in_cnt[idx], 1));
    }
}

__global__ void k_fill(const int* __restrict__ src,
                       const int* __restrict__ dst) {
    int e = blockIdx.x * blockDim.x + threadIdx.x;
    if (e < N_EDGES) {
        unsigned s = (unsigned)src[e];
        unsigned d = (unsigned)dst[e];
        if (s < N_NODES && d < N_NODES) {
            int pos = atomicAdd(&g_cursor[d], 1);
            int idx = g_off[d] + pos;
            if ((unsigned)idx < N_EDGES) g_csr_src[idx] = (int)s;
        }
    }
}

// bufA = h * out_deg^{-1/2}
__global__ void k_scale0(const float4* __restrict__ h) {
    int i = blockIdx.x * blockDim.x + threadIdx.x;
    if (i < N_NODES * NV4) {
        float sc = g_out_inv[i >> 5];
        float4 v = h[i];
        v.x *= sc; v.y *= sc; v.z *= sc; v.w *= sc;
        g_bufA[i] = v;
    }
}

// round weights to tf32 once
__global__ void k_wprep(const float* __restrict__ W0,
                        const float* __restrict__ W1,
                        const float* __restrict__ W2) {
    int i = blockIdx.x * blockDim.x + threadIdx.x;
    if (i < D * D) {
        g_Wtf[i]             = tf32r(W0[i]);
        g_Wtf[D * D + i]     = tf32r(W1[i]);
        g_Wtf[2 * D * D + i] = tf32r(W2[i]);
    }
}

// ---------------- aggregation: m[n] = tf32(in_inv[n] * sum x[src]) ----------
__global__ void __launch_bounds__(256) k_agg(int in_sel) {
    const float4* __restrict__ xin = in_sel ? g_bufB : g_bufA;
    int warp = threadIdx.x >> 5;
    int lane = threadIdx.x & 31;
    int n = blockIdx.x * 8 + warp;

    int beg = g_off[n], end = g_off[n + 1];
    float4 acc = make_float4(0.f, 0.f, 0.f, 0.f);
    int k = beg;
    for (; k + 3 < end; k += 4) {
        int s0 = g_csr_src[k + 0];
        int s1 = g_csr_src[k + 1];
        int s2 = g_csr_src[k + 2];
        int s3 = g_csr_src[k + 3];
        float4 v0 = xin[s0 * NV4 + lane];
        float4 v1 = xin[s1 * NV4 + lane];
        float4 v2 = xin[s2 * NV4 + lane];
        float4 v3 = xin[s3 * NV4 + lane];
        acc.x += v0.x + v1.x + v2.x + v3.x;
        acc.y += v0.y + v1.y + v2.y + v3.y;
        acc.z += v0.z + v1.z + v2.z + v3.z;
        acc.w += v0.w + v1.w + v2.w + v3.w;
    }
    for (; k < end; ++k) {
        int s = g_csr_src[k];
        float4 v = xin[s * NV4 + lane];
        acc.x += v.x; acc.y += v.y; acc.z += v.z; acc.w += v.w;
    }
    float sc = g_in_inv[n];
    float4 r;
    r.x = tf32r(acc.x * sc);
    r.y = tf32r(acc.y * sc);
    r.z = tf32r(acc.z * sc);
    r.w = tf32r(acc.w * sc);
    g_m[n * NV4 + lane] = r;
}

// ---------------- GEMM via mma.sync m16n8k8 tf32 ----------------
// block: 128 rows x 128 cols; warp w: rows (w&3)*32, col-half (w>>2)*64
// out = relu(m @ W + b) [* out_inv]
__global__ void __launch_bounds__(256) k_gemm_mma(int out_sel, float* __restrict__ dout,
                                                  int widx,
                                                  const float* __restrict__ bias,
                                                  int apply_out) {
    float* __restrict__ out = (out_sel == 0) ? (float*)g_bufA
                            : (out_sel == 1) ? (float*)g_bufB : dout;
    const float* __restrict__ Wt = g_Wtf + widx * D * D;
    const float* __restrict__ A  = (const float*)g_m;

    int lane = threadIdx.x & 31;
    int warp = threadIdx.x >> 5;
    int gid = lane >> 2;     // 0..7
    int tq  = lane & 3;      // 0..3
    int r0 = blockIdx.x * 128 + (warp & 3) * 32;
    int n0 = (warp >> 2) * 64;

    float acc[2][8][4];
    #pragma unroll
    for (int mi = 0; mi < 2; mi++)
        #pragma unroll
        for (int nf = 0; nf < 8; nf++)
            #pragma unroll
            for (int c = 0; c < 4; c++) acc[mi][nf][c] = 0.f;

    // clamped A rows (rows >= N_NODES read row N_NODES-1, discarded at store)
    int ra[2][2];
    ra[0][0] = min(r0 + gid,      N_NODES - 1);
    ra[0][1] = min(r0 + gid + 8,  N_NODES - 1);
    ra[1][0] = min(r0 + gid + 16, N_NODES - 1);
    ra[1][1] = min(r0 + gid + 24, N_NODES - 1);

    for (int kf = 0; kf < 16; kf++) {
        int k0 = kf * 8;
        uint32_t a[2][4];
        #pragma unroll
        for (int mi = 0; mi < 2; mi++) {
            const float* Ar0 = A + (size_t)ra[mi][0] * D + k0 + tq;
            const float* Ar1 = A + (size_t)ra[mi][1] * D + k0 + tq;
            a[mi][0] = __float_as_uint(Ar0[0]);
            a[mi][1] = __float_as_uint(Ar1[0]);
            a[mi][2] = __float_as_uint(Ar0[4]);
            a[mi][3] = __float_as_uint(Ar1[4]);
        }
        const float* B0 = Wt + (k0 + tq) * D + n0 + gid;
        const float* B1 = B0 + 4 * D;
        uint32_t bb[8][2];
        #pragma unroll
        for (int nf = 0; nf < 8; nf++) {
            bb[nf][0] = __float_as_uint(B0[nf * 8]);
            bb[nf][1] = __float_as_uint(B1[nf * 8]);
        }
        #pragma unroll
        for (int mi = 0; mi < 2; mi++)
            #pragma unroll
            for (int nf = 0; nf < 8; nf++)
                asm volatile(
                    "mma.sync.aligned.m16n8k8.row.col.f32.tf32.tf32.f32 "
                    "{%0,%1,%2,%3}, {%4,%5,%6,%7}, {%8,%9}, {%0,%1,%2,%3};"
                    : "+f"(acc[mi][nf][0]), "+f"(acc[mi][nf][1]),
                      "+f"(acc[mi][nf][2]), "+f"(acc[mi][nf][3])
                    : "r"(a[mi][0]), "r"(a[mi][1]), "r"(a[mi][2]), "r"(a[mi][3]),
                      "r"(bb[nf][0]), "r"(bb[nf][1]));
    }

    // epilogue: bias + relu (+ out_inv scale), float2 stores
    #pragma unroll
    for (int mi = 0; mi < 2; mi++) {
        int rowA = r0 + mi * 16 + gid;
        int rowB = rowA + 8;
        float s0 = 1.f, s1 = 1.f;
        if (apply_out) {
            s0 = g_out_inv[min(rowA, N_NODES - 1)];
            s1 = g_out_inv[min(rowB, N_NODES - 1)];
        }
        #pragma unroll
        for (int nf = 0; nf < 8; nf++) {
            int col = n0 + nf * 8 + 2 * tq;
            float2 bv = *(const float2*)(bias + col);
            float v0 = fmaxf(acc[mi][nf][0] + bv.x, 0.f) * s0;
            float v1 = fmaxf(acc[mi][nf][1] + bv.y, 0.f) * s0;
            float v2 = fmaxf(acc[mi][nf][2] + bv.x, 0.f) * s1;
            float v3 = fmaxf(acc[mi][nf][3] + bv.y, 0.f) * s1;
            if (rowA < N_NODES)
                *(float2*)(out + (size_t)rowA * D + col) = make_float2(v0, v1);
            if (rowB < N_NODES)
                *(float2*)(out + (size_t)rowB * D + col) = make_float2(v2, v3);
        }
    }
}

extern "C" void kernel_launch(void* const* d_in, const int* in_sizes, int n_in,
                              void* d_out, int out_size) {
    const float* h   = (const float*)d_in[0];
    const int*   src = (const int*)d_in[1];    // int32: JAX x64 is disabled
    const int*   dst = (const int*)d_in[2];
    const float* W0 = (const float*)d_in[3];
    const float* b0 = (const float*)d_in[4];
    const float* W1 = (const float*)d_in[5];
    const float* b1 = (const float*)d_in[6];
    const float* W2 = (const float*)d_in[7];
    const float* b2 = (const float*)d_in[8];

    k_init<<<(N_NODES + 255) / 256, 256>>>();
    k_deg<<<(N_EDGES + 255) / 256, 256>>>(src, dst);
    k_scan<<<1, 1024>>>();
    k_fill<<<(N_EDGES + 255) / 256, 256>>>(src, dst);
    k_scale0<<<(N_NODES * NV4 + 255) / 256, 256>>>((const float4*)h);
    k_wprep<<<(D * D + 255) / 256, 256>>>(W0, W1, W2);

    const int agg_grid  = N_NODES / 8;              // 6250, exact
    const int gemm_grid = (N_NODES + 127) / 128;    // 391

    // layer 0: bufA -> m -> bufB (out-scaled for next layer)
    k_agg     <<<agg_grid, 256>>>(0);
    k_gemm_mma<<<gemm_grid, 256>>>(1, nullptr, 0, b0, 1);
    // layer 1: bufB -> m -> bufA (out-scaled)
    k_agg     <<<agg_grid, 256>>>(1);
    k_gemm_mma<<<gemm_grid, 256>>>(0, nullptr, 1, b1, 1);
    // layer 2: bufA -> m -> d_out (no out-scale)
    k_agg     <<<agg_grid, 256>>>(0);
    k_gemm_mma<<<gemm_grid, 256>>>(2, (float*)d_out, 2, b2, 0);
}

// round 7
// speedup vs baseline: 1.2031x; 1.0778x over previous
#include <cuda_runtime.h>
#include <cuda_bf16.h>
#include <cstdint>

#define N_NODES 50000
#define N_EDGES 800000
#define NV4 32            // float4 per 128-float row
#define D 128

// ---- device scratch (no dynamic allocs allowed) ----
__device__ float4 g_bufA[(size_t)N_NODES * NV4];
__device__ float4 g_bufB[(size_t)N_NODES * NV4];
__device__ float4 g_m   [(size_t)N_NODES * NV4];   // tf32-rounded aggregate
__device__ float2 g_Wf  [3 * 8192];                // fragment-major tf32 weights
__device__ int    g_out_cnt[N_NODES];
__device__ int    g_in_cnt[N_NODES];
__device__ int    g_cursor[N_NODES];
__device__ int    g_off[N_NODES + 1];
__device__ int    g_csr_src[N_EDGES];
__device__ float  g_out_inv[N_NODES];
__device__ float  g_in_inv[N_NODES];

__device__ __forceinline__ float tf32r(float x) {
    uint32_t u;
    asm("cvt.rna.tf32.f32 %0, %1;" : "=r"(u) : "f"(x));
    return __uint_as_float(u);
}

// ---------------- CSR build ----------------
__global__ void k_init() {
    int i = blockIdx.x * blockDim.x + threadIdx.x;
    if (i < N_NODES) { g_out_cnt[i] = 0; g_in_cnt[i] = 0; g_cursor[i] = 0; }
}

__global__ void k_deg(const int* __restrict__ src,
                      const int* __restrict__ dst) {
    int e = blockIdx.x * blockDim.x + threadIdx.x;
    if (e < N_EDGES) {
        unsigned s = (unsigned)src[e];
        unsigned d = (unsigned)dst[e];
        if (s < N_NODES) atomicAdd(&g_out_cnt[s], 1);
        if (d < N_NODES) atomicAdd(&g_in_cnt[d], 1);
    }
}

__global__ void k_scan() {
    const int T = 1024;
    const int CH = (N_NODES + T - 1) / T;
    __shared__ int part[T];
    int t = threadIdx.x;
    int base = t * CH;
    int s = 0;
    for (int i = 0; i < CH; i++) {
        int idx = base + i;
        if (idx < N_NODES) s += g_in_cnt[idx];
    }
    part[t] = s;
    __syncthreads();
    for (int o = 1; o < T; o <<= 1) {
        int v = (t >= o) ? part[t - o] : 0;
        __syncthreads();
        part[t] += v;
        __syncthreads();
    }
    int run = (t == 0) ? 0 : part[t - 1];
    for (int i = 0; i < CH; i++) {
        int idx = base + i;
        if (idx < N_NODES) { g_off[idx] = run; run += g_in_cnt[idx]; }
    }
    if (t == T - 1) g_off[N_NODES] = run;
    for (int idx = t; idx < N_NODES; idx += T) {
        g_out_inv[idx] = rsqrtf((float)max(g_out_cnt[idx], 1));
        g_in_inv[idx]  = rsqrtf((float)max(g_in_cnt[idx], 1));
    }
}

__global__ void k_fill(const int* __restrict__ src,
                       const int* __restrict__ dst) {
    int e = blockIdx.x * blockDim.x + threadIdx.x;
    if (e < N_EDGES) {
        unsigned s = (unsigned)src[e];
        unsigned d = (unsigned)dst[e];
        if (s < N_NODES && d < N_NODES) {
            int pos = atomicAdd(&g_cursor[d], 1);
            int idx = g_off[d] + pos;
            if ((unsigned)idx < N_EDGES) g_csr_src[idx] = (int)s;
        }
    }
}

// rearrange W into fragment-major tf32: for (kf,nf,lane): tq=lane&3, gid=lane>>2
//   b0 = W[kf*8+tq][nf*8+gid], b1 = W[kf*8+tq+4][nf*8+gid]
__global__ void k_wprep(const float* __restrict__ W0,
                        const float* __restrict__ W1,
                        const float* __restrict__ W2) {
    int i = blockIdx.x * blockDim.x + threadIdx.x;
    if (i >= 3 * 8192) return;
    int l    = i >> 13;
    int r    = i & 8191;
    int kf   = r >> 9;
    int nf   = (r >> 5) & 15;
    int lane = r & 31;
    int tq = lane & 3, gid = lane >> 2;
    const float* W = (l == 0) ? W0 : (l == 1) ? W1 : W2;
    float b0 = W[(kf * 8 + tq) * D + nf * 8 + gid];
    float b1 = W[(kf * 8 + tq + 4) * D + nf * 8 + gid];
    g_Wf[i] = make_float2(tf32r(b0), tf32r(b1));
}

// ---------------- aggregation: m[n] = tf32(in_inv[n] * sum x[src] [*out_inv[src]]) ----
// xg != nullptr -> gather from xg (layer 0, apply out_inv per src)
__global__ void __launch_bounds__(256) k_agg(const float4* __restrict__ xg,
                                             int in_sel, int scale_src) {
    const float4* __restrict__ xin = xg ? xg : (in_sel ? g_bufB : g_bufA);
    int warp = threadIdx.x >> 5;
    int lane = threadIdx.x & 31;
    int n = blockIdx.x * 8 + warp;

    int beg = g_off[n], end = g_off[n + 1];
    float4 acc = make_float4(0.f, 0.f, 0.f, 0.f);
    int k = beg;
    for (; k + 3 < end; k += 4) {
        int s0 = g_csr_src[k + 0];
        int s1 = g_csr_src[k + 1];
        int s2 = g_csr_src[k + 2];
        int s3 = g_csr_src[k + 3];
        float w0 = 1.f, w1 = 1.f, w2 = 1.f, w3 = 1.f;
        if (scale_src) {
            w0 = g_out_inv[s0]; w1 = g_out_inv[s1];
            w2 = g_out_inv[s2]; w3 = g_out_inv[s3];
        }
        float4 v0 = xin[s0 * NV4 + lane];
        float4 v1 = xin[s1 * NV4 + lane];
        float4 v2 = xin[s2 * NV4 + lane];
        float4 v3 = xin[s3 * NV4 + lane];
        acc.x = fmaf(v0.x, w0, fmaf(v1.x, w1, fmaf(v2.x, w2, fmaf(v3.x, w3, acc.x))));
        acc.y = fmaf(v0.y, w0, fmaf(v1.y, w1, fmaf(v2.y, w2, fmaf(v3.y, w3, acc.y))));
        acc.z = fmaf(v0.z, w0, fmaf(v1.z, w1, fmaf(v2.z, w2, fmaf(v3.z, w3, acc.z))));
        acc.w = fmaf(v0.w, w0, fmaf(v1.w, w1, fmaf(v2.w, w2, fmaf(v3.w, w3, acc.w))));
    }
    for (; k < end; ++k) {
        int s = g_csr_src[k];
        float w = scale_src ? g_out_inv[s] : 1.f;
        float4 v = xin[s * NV4 + lane];
        acc.x = fmaf(v.x, w, acc.x);
        acc.y = fmaf(v.y, w, acc.y);
        acc.z = fmaf(v.z, w, acc.z);
        acc.w = fmaf(v.w, w, acc.w);
    }
    float sc = g_in_inv[n];
    float4 r;
    r.x = tf32r(acc.x * sc);
    r.y = tf32r(acc.y * sc);
    r.z = tf32r(acc.z * sc);
    r.w = tf32r(acc.w * sc);
    g_m[n * NV4 + lane] = r;
}

// ---------------- GEMM via mma.sync m16n8k8 tf32, smem A-tile + fragment-major W ----
// block: 128 rows x 128 cols; warp w: rows w*16..w*16+15, all 128 cols
__global__ void __launch_bounds__(256, 2)
k_gemm2(int out_sel, float* __restrict__ dout, int widx,
        const float* __restrict__ bias, int apply_out) {
    __shared__ __align__(16) float As[128 * 36];   // 128 rows x 32 k, pad 4

    float* __restrict__ out = (out_sel == 0) ? (float*)g_bufA
                            : (out_sel == 1) ? (float*)g_bufB : dout;
    const float2* __restrict__ Wf = g_Wf + widx * 8192;

    int lane = threadIdx.x & 31;
    int warp = threadIdx.x >> 5;
    int gid = lane >> 2;     // 0..7
    int tq  = lane & 3;      // 0..3
    int row0 = blockIdx.x * 128;

    float acc[16][4];
    #pragma unroll
    for (int nf = 0; nf < 16; nf++)
        #pragma unroll
        for (int c = 0; c < 4; c++) acc[nf][c] = 0.f;

    int lr = threadIdx.x >> 1;                 // 0..127 row within tile
    int lc = (threadIdx.x & 1) * 16;           // 0 or 16 k-offset
    int grow = min(row0 + lr, N_NODES - 1);
    const float* gbase = (const float*)g_m + (size_t)grow * D + lc;

    for (int kt = 0; kt < 128; kt += 32) {
        float4 v0 = *(const float4*)(gbase + kt);
        float4 v1 = *(const float4*)(gbase + kt + 4);
        float4 v2 = *(const float4*)(gbase + kt + 8);
        float4 v3 = *(const float4*)(gbase + kt + 12);
        __syncthreads();
        float* dstp = As + lr * 36 + lc;
        ((float4*)dstp)[0] = v0;
        ((float4*)dstp)[1] = v1;
        ((float4*)dstp)[2] = v2;
        ((float4*)dstp)[3] = v3;
        __syncthreads();

        #pragma unroll
        for (int kf2 = 0; kf2 < 4; kf2++) {
            const float* Ab = As + (warp * 16 + gid) * 36 + kf2 * 8 + tq;
            uint32_t a0 = __float_as_uint(Ab[0]);
            uint32_t a1 = __float_as_uint(Ab[8 * 36]);
            uint32_t a2 = __float_as_uint(Ab[4]);
            uint32_t a3 = __float_as_uint(Ab[8 * 36 + 4]);
            int kf = (kt >> 3) + kf2;
            const float2* Wk = Wf + (kf << 9) + lane;
            #pragma unroll
            for (int nf = 0; nf < 16; nf++) {
                float2 b = Wk[nf * 32];        // coalesced LDG.64, L1-resident
                asm volatile(
                    "mma.sync.aligned.m16n8k8.row.col.f32.tf32.tf32.f32 "
                    "{%0,%1,%2,%3}, {%4,%5,%6,%7}, {%8,%9}, {%0,%1,%2,%3};"
                    : "+f"(acc[nf][0]), "+f"(acc[nf][1]),
                      "+f"(acc[nf][2]), "+f"(acc[nf][3])
                    : "r"(a0), "r"(a1), "r"(a2), "r"(a3),
                      "r"(__float_as_uint(b.x)), "r"(__float_as_uint(b.y)));
            }
        }
    }

    // epilogue: bias + relu (+ out_inv), float2 stores
    int rowA = row0 + warp * 16 + gid;
    int rowB = rowA + 8;
    float s0 = 1.f, s1 = 1.f;
    if (apply_out) {
        s0 = g_out_inv[min(rowA, N_NODES - 1)];
        s1 = g_out_inv[min(rowB, N_NODES - 1)];
    }
    #pragma unroll
    for (int nf = 0; nf < 16; nf++) {
        int col = nf * 8 + 2 * tq;
        float2 bv = *(const float2*)(bias + col);
        float v0 = fmaxf(acc[nf][0] + bv.x, 0.f) * s0;
        float v1 = fmaxf(acc[nf][1] + bv.y, 0.f) * s0;
        float v2 = fmaxf(acc[nf][2] + bv.x, 0.f) * s1;
        float v3 = fmaxf(acc[nf][3] + bv.y, 0.f) * s1;
        if (rowA < N_NODES)
            *(float2*)(out + (size_t)rowA * D + col) = make_float2(v0, v1);
        if (rowB < N_NODES)
            *(float2*)(out + (size_t)rowB * D + col) = make_float2(v2, v3);
    }
}

extern "C" void kernel_launch(void* const* d_in, const int* in_sizes, int n_in,
                              void* d_out, int out_size) {
    const float* h   = (const float*)d_in[0];
    const int*   src = (const int*)d_in[1];    // int32: JAX x64 is disabled
    const int*   dst = (const int*)d_in[2];
    const float* W0 = (const float*)d_in[3];
    const float* b0 = (const float*)d_in[4];
    const float* W1 = (const float*)d_in[5];
    const float* b1 = (const float*)d_in[6];
    const float* W2 = (const float*)d_in[7];
    const float* b2 = (const float*)d_in[8];

    k_init<<<(N_NODES + 255) / 256, 256>>>();
    k_deg<<<(N_EDGES + 255) / 256, 256>>>(src, dst);
    k_scan<<<1, 1024>>>();
    k_fill<<<(N_EDGES + 255) / 256, 256>>>(src, dst);
    k_wprep<<<(3 * 8192 + 255) / 256, 256>>>(W0, W1, W2);

    const int agg_grid  = N_NODES / 8;              // 6250, exact
    const int gemm_grid = (N_NODES + 127) / 128;    // 391

    // layer 0: h (src-scaled in gather) -> m -> bufB (out-scaled)
    k_agg  <<<agg_grid, 256>>>((const float4*)h, 0, 1);
    k_gemm2<<<gemm_grid, 256>>>(1, nullptr, 0, b0, 1);
    // layer 1: bufB -> m -> bufA (out-scaled)
    k_agg  <<<agg_grid, 256>>>(nullptr, 1, 0);
    k_gemm2<<<gemm_grid, 256>>>(0, nullptr, 1, b1, 1);
    // layer 2: bufA -> m -> d_out (no out-scale)
    k_agg  <<<agg_grid, 256>>>(nullptr, 0, 0);
    k_gemm2<<<gemm_grid, 256>>>(2, (float*)d_out, 2, b2, 0);
}